// round 4
// baseline (speedup 1.0000x reference)
#include <cuda_runtime.h>
#include <cuda_bf16.h>
#include <cstdint>
#include <math.h>

// Problem dims (fixed by the dataset)
#define BB 16
#define SS 1024
#define HH 512
#define CC 7
#define MM (BB * SS)        // 16384 rows
#define H3 (3 * HH)         // 1536
#define EPSV 1e-10f

// GEMM tiling
#define BM 128
#define BN 128
#define BK 32
#define LDA 40              // halves, padded (80B = 5x16B rows: cp.async-aligned, ldmatrix conflict-free)
#define LDB 136             // halves, padded (272B = 17x16B rows)

#define SMEM_BYTES ((2 * BM * LDA + 2 * BM * LDA + 2 * BK * LDB + 2 * BK * LDB) * 2)

// ----------------------------------------------------------------------------
// Static scratch (bf16 hi/lo planes; no allocations anywhere)
// ----------------------------------------------------------------------------
__device__ __nv_bfloat16 g_fh[3 * MM * HH],  g_fl[3 * MM * HH];    // text/audio/visual
__device__ __nv_bfloat16 g_toth[MM * HH],    g_totl[MM * HH];
__device__ __nv_bfloat16 g_Gh[3 * MM * HH],  g_Gl[3 * MM * HH];
__device__ __nv_bfloat16 g_Th[MM * HH],      g_Tl[MM * HH];
__device__ __nv_bfloat16 g_h0h[MM * H3],     g_h0l[MM * H3];
__device__ __nv_bfloat16 g_adjh[BB * SS * SS], g_adjl[BB * SS * SS];
__device__ __nv_bfloat16 g_tmph[MM * HH],    g_tmpl[MM * HH];
__device__ __nv_bfloat16 g_hh[MM * HH],      g_hl[MM * HH];
__device__ __nv_bfloat16 g_Awh[HH * HH], g_Awl[HH * HH];
__device__ __nv_bfloat16 g_Whh[HH * HH], g_Whl[HH * HH];
__device__ __nv_bfloat16 g_W0h[H3 * HH], g_W0l[H3 * HH];
__device__ __nv_bfloat16 g_W1h[HH * HH], g_W1l[HH * HH];
__device__ __nv_bfloat16 g_W2h[HH * HH], g_W2l[HH * HH];
__device__ float g_ent[3 * MM];
__device__ float g_dsi[BB * SS];
__device__ float g_wlast[HH];
__device__ float g_WcT[CC * HH];

// ----------------------------------------------------------------------------
// Helpers
// ----------------------------------------------------------------------------
__device__ __forceinline__ unsigned s2u(const void* p) {
    return (unsigned)__cvta_generic_to_shared(p);
}

__device__ __forceinline__ void split4_store(float4 v, __nv_bfloat16* h,
                                             __nv_bfloat16* l, long long idx) {
    __nv_bfloat16 hx = __float2bfloat16(v.x);
    __nv_bfloat16 hy = __float2bfloat16(v.y);
    __nv_bfloat16 hz = __float2bfloat16(v.z);
    __nv_bfloat16 hw = __float2bfloat16(v.w);
    __nv_bfloat16 lx = __float2bfloat16(v.x - __bfloat162float(hx));
    __nv_bfloat16 ly = __float2bfloat16(v.y - __bfloat162float(hy));
    __nv_bfloat16 lz = __float2bfloat16(v.z - __bfloat162float(hz));
    __nv_bfloat16 lw = __float2bfloat16(v.w - __bfloat162float(hw));
    __nv_bfloat162* ph = (__nv_bfloat162*)(h + idx);
    __nv_bfloat162* pl = (__nv_bfloat162*)(l + idx);
    ph[0] = __nv_bfloat162(hx, hy); ph[1] = __nv_bfloat162(hz, hw);
    pl[0] = __nv_bfloat162(lx, ly); pl[1] = __nv_bfloat162(lz, lw);
}

#define MMA16816(d, a, b)                                                  \
    asm volatile(                                                          \
        "mma.sync.aligned.m16n8k16.row.col.f32.bf16.bf16.f32 "             \
        "{%0,%1,%2,%3}, {%4,%5,%6,%7}, {%8,%9}, {%0,%1,%2,%3};\n"          \
        : "+f"(d[0]), "+f"(d[1]), "+f"(d[2]), "+f"(d[3])                   \
        : "r"(a[0]), "r"(a[1]), "r"(a[2]), "r"(a[3]), "r"(b[0]), "r"(b[1]))

#define LDSM_X4(r0, r1, r2, r3, addr)                                      \
    asm volatile("ldmatrix.sync.aligned.m8n8.x4.shared.b16 "               \
                 "{%0,%1,%2,%3}, [%4];\n"                                  \
                 : "=r"(r0), "=r"(r1), "=r"(r2), "=r"(r3) : "r"(addr))

#define LDSM_X4T(r0, r1, r2, r3, addr)                                     \
    asm volatile("ldmatrix.sync.aligned.m8n8.x4.trans.shared.b16 "         \
                 "{%0,%1,%2,%3}, [%4];\n"                                  \
                 : "=r"(r0), "=r"(r1), "=r"(r2), "=r"(r3) : "r"(addr))

#define CP16(dst, src)                                                     \
    asm volatile("cp.async.cg.shared.global [%0], [%1], 16;\n"             \
                 :: "r"(dst), "l"(src))
#define CP_COMMIT asm volatile("cp.async.commit_group;\n" ::: "memory")
#define CP_WAIT(n) asm volatile("cp.async.wait_group %0;\n" :: "n"(n) : "memory")

// ----------------------------------------------------------------------------
// Fused: entropy + bf16 split of feats + total   (one read of the 3 feats)
// ----------------------------------------------------------------------------
__global__ void prep_feats(const float* __restrict__ text,
                           const float* __restrict__ audio,
                           const float* __restrict__ visual) {
    __shared__ float sh[3][4];
    long long r = blockIdx.x;
    int tid = threadIdx.x, lane = tid & 31, w = tid >> 5;
    const float* fp0 = text; const float* fp1 = audio; const float* fp2 = visual;
    long long off = r * HH + tid * 4;
    float4 v0 = *(const float4*)(fp0 + off);
    float4 v1 = *(const float4*)(fp1 + off);
    float4 v2 = *(const float4*)(fp2 + off);

    float a0x = fabsf(v0.x), a0y = fabsf(v0.y), a0z = fabsf(v0.z), a0w = fabsf(v0.w);
    float a1x = fabsf(v1.x), a1y = fabsf(v1.y), a1z = fabsf(v1.z), a1w = fabsf(v1.w);
    float a2x = fabsf(v2.x), a2y = fabsf(v2.y), a2z = fabsf(v2.z), a2w = fabsf(v2.w);
    float s0 = a0x + a0y + a0z + a0w;
    float s1 = a1x + a1y + a1z + a1w;
    float s2 = a2x + a2y + a2z + a2w;
    #pragma unroll
    for (int o = 16; o; o >>= 1) {
        s0 += __shfl_down_sync(0xffffffffu, s0, o);
        s1 += __shfl_down_sync(0xffffffffu, s1, o);
        s2 += __shfl_down_sync(0xffffffffu, s2, o);
    }
    if (lane == 0) { sh[0][w] = s0; sh[1][w] = s1; sh[2][w] = s2; }
    __syncthreads();
    float t0 = sh[0][0] + sh[0][1] + sh[0][2] + sh[0][3];
    float t1 = sh[1][0] + sh[1][1] + sh[1][2] + sh[1][3];
    float t2 = sh[2][0] + sh[2][1] + sh[2][2] + sh[2][3];
    float i0 = 1.0f / (t0 + EPSV), i1 = 1.0f / (t1 + EPSV), i2 = 1.0f / (t2 + EPSV);

    float e0, e1, e2;
    {
        float f0 = a0x * i0, f1 = a0y * i0, f2 = a0z * i0, f3 = a0w * i0;
        e0 = f0 * logf(f0 + EPSV) + f1 * logf(f1 + EPSV)
           + f2 * logf(f2 + EPSV) + f3 * logf(f3 + EPSV);
    }
    {
        float f0 = a1x * i1, f1 = a1y * i1, f2 = a1z * i1, f3 = a1w * i1;
        e1 = f0 * logf(f0 + EPSV) + f1 * logf(f1 + EPSV)
           + f2 * logf(f2 + EPSV) + f3 * logf(f3 + EPSV);
    }
    {
        float f0 = a2x * i2, f1 = a2y * i2, f2 = a2z * i2, f3 = a2w * i2;
        e2 = f0 * logf(f0 + EPSV) + f1 * logf(f1 + EPSV)
           + f2 * logf(f2 + EPSV) + f3 * logf(f3 + EPSV);
    }
    #pragma unroll
    for (int o = 16; o; o >>= 1) {
        e0 += __shfl_down_sync(0xffffffffu, e0, o);
        e1 += __shfl_down_sync(0xffffffffu, e1, o);
        e2 += __shfl_down_sync(0xffffffffu, e2, o);
    }
    __syncthreads();
    if (lane == 0) { sh[0][w] = e0; sh[1][w] = e1; sh[2][w] = e2; }
    __syncthreads();
    if (tid == 0) {
        g_ent[0 * MM + r] = -(sh[0][0] + sh[0][1] + sh[0][2] + sh[0][3]);
        g_ent[1 * MM + r] = -(sh[1][0] + sh[1][1] + sh[1][2] + sh[1][3]);
        g_ent[2 * MM + r] = -(sh[2][0] + sh[2][1] + sh[2][2] + sh[2][3]);
    }

    // bf16 splits
    split4_store(v0, g_fh, g_fl, 0LL * MM * HH + off);
    split4_store(v1, g_fh, g_fl, 1LL * MM * HH + off);
    split4_store(v2, g_fh, g_fl, 2LL * MM * HH + off);
    float4 tq = make_float4(v0.x + v1.x + v2.x, v0.y + v1.y + v2.y,
                            v0.z + v1.z + v2.z, v0.w + v1.w + v2.w);
    split4_store(tq, g_toth, g_totl, off);
}

// ----------------------------------------------------------------------------
// Weight prep: Aw = Wa+Wb-0.5*Wc ; Wh = 0.5*Wc   (split to bf16 hi/lo)
// ----------------------------------------------------------------------------
__global__ void prep_weights(const float* __restrict__ gW) {
    int idx = blockIdx.x * blockDim.x + threadIdx.x;
    if (idx < HH * HH) {
        float wa = gW[idx];
        float wb = gW[HH * HH + idx];
        float wc = gW[2 * HH * HH + idx];
        float aw = wa + wb - 0.5f * wc;
        float wh = 0.5f * wc;
        __nv_bfloat16 h1 = __float2bfloat16(aw);
        g_Awh[idx] = h1; g_Awl[idx] = __float2bfloat16(aw - __bfloat162float(h1));
        __nv_bfloat16 h2 = __float2bfloat16(wh);
        g_Whh[idx] = h2; g_Whl[idx] = __float2bfloat16(wh - __bfloat162float(h2));
    }
    if (idx < HH) g_wlast[idx] = gW[3 * HH * HH + idx];
}

__global__ void conv_w(const float* __restrict__ src, __nv_bfloat16* __restrict__ h,
                       __nv_bfloat16* __restrict__ l, int n4) {
    int i = blockIdx.x * blockDim.x + threadIdx.x;
    if (i < n4) {
        float4 v = ((const float4*)src)[i];
        split4_store(v, h, l, (long long)i * 4);
    }
}

__global__ void transpose_wc(const float* __restrict__ Wc) {
    int idx = blockIdx.x * blockDim.x + threadIdx.x;
    if (idx < HH * CC) {
        int k = idx / CC, c = idx % CC;
        g_WcT[c * HH + k] = Wc[k * CC + c];
    }
}

// ----------------------------------------------------------------------------
// bf16-split tensor-core GEMM, cp.async double-buffered.
// C = A @ B (+bias+relu). All operands as bf16 hi/lo planes. 3 MMAs / logical.
// ----------------------------------------------------------------------------
template <int EPI>   // 0 = none, 1 = bias+relu
__global__ void __launch_bounds__(256) mma_gemm(
    const __nv_bfloat16* __restrict__ Ahg, const __nv_bfloat16* __restrict__ Alg,
    const __nv_bfloat16* __restrict__ Bhg, const __nv_bfloat16* __restrict__ Blg,
    const float* __restrict__ bias,
    __nv_bfloat16* __restrict__ Chg, __nv_bfloat16* __restrict__ Clg,
    int M, int N, int K, long long sA, long long sB, long long sC)
{
    extern __shared__ char smem[];
    __nv_bfloat16* sAh = (__nv_bfloat16*)smem;                // [2][BM*LDA]
    __nv_bfloat16* sAl = sAh + 2 * BM * LDA;
    __nv_bfloat16* sBh = sAl + 2 * BM * LDA;                  // [2][BK*LDB]
    __nv_bfloat16* sBl = sBh + 2 * BK * LDB;

    const __nv_bfloat16* Ah = Ahg + (long long)blockIdx.z * sA;
    const __nv_bfloat16* Al = Alg + (long long)blockIdx.z * sA;
    const __nv_bfloat16* Bh = Bhg + (long long)blockIdx.z * sB;
    const __nv_bfloat16* Bl = Blg + (long long)blockIdx.z * sB;
    __nv_bfloat16* Ch = Chg + (long long)blockIdx.z * sC;
    __nv_bfloat16* Cl = Clg + (long long)blockIdx.z * sC;

    int t = threadIdx.x, lane = t & 31, wid = t >> 5;
    int warp_m = wid >> 2, warp_n = wid & 3;    // 2 x 4 warps
    int brow = blockIdx.y * BM, bcol = blockIdx.x * BN;
    int KT = K / BK;

    float acc[4][4][4];
    #pragma unroll
    for (int i = 0; i < 4; i++)
        #pragma unroll
        for (int j = 0; j < 4; j++)
            #pragma unroll
            for (int q = 0; q < 4; q++) acc[i][j][q] = 0.0f;

    // tile loader: 8x cp.async 16B per thread
    auto load_tile = [&](int kt, int buf) {
        int k0 = kt * BK;
        #pragma unroll
        for (int i = 0; i < 2; i++) {
            int q = t + i * 256;
            int ra = q >> 2, ca = (q & 3) << 3;         // A: 128 rows x 4 chunks
            long long asrc = (long long)(brow + ra) * K + k0 + ca;
            CP16(s2u(&sAh[buf * BM * LDA + ra * LDA + ca]), Ah + asrc);
            CP16(s2u(&sAl[buf * BM * LDA + ra * LDA + ca]), Al + asrc);
            int rb = q >> 4, cb = (q & 15) << 3;        // B: 32 rows x 16 chunks
            long long bsrc = (long long)(k0 + rb) * N + bcol + cb;
            CP16(s2u(&sBh[buf * BK * LDB + rb * LDB + cb]), Bh + bsrc);
            CP16(s2u(&sBl[buf * BK * LDB + rb * LDB + cb]), Bl + bsrc);
        }
    };

    load_tile(0, 0); CP_COMMIT;

    for (int kt = 0; kt < KT; kt++) {
        int buf = kt & 1;
        if (kt + 1 < KT) { load_tile(kt + 1, buf ^ 1); CP_COMMIT; CP_WAIT(1); }
        else             { CP_WAIT(0); }
        __syncthreads();

        const __nv_bfloat16* cAh = sAh + buf * BM * LDA;
        const __nv_bfloat16* cAl = sAl + buf * BM * LDA;
        const __nv_bfloat16* cBh = sBh + buf * BK * LDB;
        const __nv_bfloat16* cBl = sBl + buf * BK * LDB;

        #pragma unroll
        for (int kk = 0; kk < BK; kk += 16) {
            unsigned ah[4][4], al[4][4], bh[4][2], bl[4][2];
            int arow = warp_m * 64 + (lane & 15);
            int acol = kk + ((lane >> 4) << 3);
            #pragma unroll
            for (int tm = 0; tm < 4; tm++) {
                LDSM_X4(ah[tm][0], ah[tm][1], ah[tm][2], ah[tm][3],
                        s2u(&cAh[(arow + tm * 16) * LDA + acol]));
                LDSM_X4(al[tm][0], al[tm][1], al[tm][2], al[tm][3],
                        s2u(&cAl[(arow + tm * 16) * LDA + acol]));
            }
            int brow_ = kk + (lane & 15);
            #pragma unroll
            for (int tp = 0; tp < 2; tp++) {
                int bc = warp_n * 32 + tp * 16 + ((lane >> 4) << 3);
                LDSM_X4T(bh[2 * tp][0], bh[2 * tp][1],
                         bh[2 * tp + 1][0], bh[2 * tp + 1][1],
                         s2u(&cBh[brow_ * LDB + bc]));
                LDSM_X4T(bl[2 * tp][0], bl[2 * tp][1],
                         bl[2 * tp + 1][0], bl[2 * tp + 1][1],
                         s2u(&cBl[brow_ * LDB + bc]));
            }
            #pragma unroll
            for (int tm = 0; tm < 4; tm++)
                #pragma unroll
                for (int tn = 0; tn < 4; tn++) {
                    MMA16816(acc[tm][tn], ah[tm], bh[tn]);
                    MMA16816(acc[tm][tn], ah[tm], bl[tn]);
                    MMA16816(acc[tm][tn], al[tm], bh[tn]);
                }
        }
        __syncthreads();
    }

    // ---- epilogue: (bias+relu) then split to hi/lo planes ----
    int g = lane >> 2, tig = lane & 3;
    #pragma unroll
    for (int tm = 0; tm < 4; tm++)
        #pragma unroll
        for (int tn = 0; tn < 4; tn++) {
            int row = brow + warp_m * 64 + tm * 16 + g;
            int col = bcol + warp_n * 32 + tn * 8 + tig * 2;
            float2 v0 = make_float2(acc[tm][tn][0], acc[tm][tn][1]);
            float2 v1 = make_float2(acc[tm][tn][2], acc[tm][tn][3]);
            if (EPI == 1) {
                float b0 = bias[col], b1 = bias[col + 1];
                v0.x = fmaxf(v0.x + b0, 0.0f); v0.y = fmaxf(v0.y + b1, 0.0f);
                v1.x = fmaxf(v1.x + b0, 0.0f); v1.y = fmaxf(v1.y + b1, 0.0f);
            }
            #pragma unroll
            for (int rr = 0; rr < 2; rr++) {
                float2 v = rr ? v1 : v0;
                long long idx = (long long)(row + rr * 8) * N + col;
                __nv_bfloat16 h0 = __float2bfloat16(v.x);
                __nv_bfloat16 h1 = __float2bfloat16(v.y);
                __nv_bfloat16 l0 = __float2bfloat16(v.x - __bfloat162float(h0));
                __nv_bfloat16 l1 = __float2bfloat16(v.y - __bfloat162float(h1));
                *(__nv_bfloat162*)(Ch + idx) = __nv_bfloat162(h0, h1);
                *(__nv_bfloat162*)(Cl + idx) = __nv_bfloat162(l0, l1);
            }
        }
}

// ----------------------------------------------------------------------------
// gate_fuse: h0 = sigmoid(G + T + ent*wlast + gate_b) * feat   -> hi/lo planes
// ----------------------------------------------------------------------------
__global__ void gate_fuse_kernel(const float* __restrict__ gate_b,
                                 const float* __restrict__ text,
                                 const float* __restrict__ audio,
                                 const float* __restrict__ visual) {
    long long r = blockIdx.x;
    int m = blockIdx.y;
    const float* feat = (m == 0) ? text : (m == 1) ? audio : visual;
    float e = g_ent[(long long)m * MM + r];
    int j = threadIdx.x * 4;
    long long gi = ((long long)m * MM + r) * HH + j;
    __nv_bfloat162 gh0 = *(const __nv_bfloat162*)(g_Gh + gi);
    __nv_bfloat162 gh1 = *(const __nv_bfloat162*)(g_Gh + gi + 2);
    __nv_bfloat162 gl0 = *(const __nv_bfloat162*)(g_Gl + gi);
    __nv_bfloat162 gl1 = *(const __nv_bfloat162*)(g_Gl + gi + 2);
    long long ti = r * HH + j;
    __nv_bfloat162 th0 = *(const __nv_bfloat162*)(g_Th + ti);
    __nv_bfloat162 th1 = *(const __nv_bfloat162*)(g_Th + ti + 2);
    __nv_bfloat162 tl0 = *(const __nv_bfloat162*)(g_Tl + ti);
    __nv_bfloat162 tl1 = *(const __nv_bfloat162*)(g_Tl + ti + 2);
    float4 wv = *(const float4*)(g_wlast + j);
    float4 bv = *(const float4*)(gate_b + j);
    float4 fv = *(const float4*)(feat + r * HH + j);

    float gx = __bfloat162float(gh0.x) + __bfloat162float(gl0.x);
    float gy = __bfloat162float(gh0.y) + __bfloat162float(gl0.y);
    float gz = __bfloat162float(gh1.x) + __bfloat162float(gl1.x);
    float gw = __bfloat162float(gh1.y) + __bfloat162float(gl1.y);
    float tx = __bfloat162float(th0.x) + __bfloat162float(tl0.x);
    float ty = __bfloat162float(th0.y) + __bfloat162float(tl0.y);
    float tz = __bfloat162float(th1.x) + __bfloat162float(tl1.x);
    float tw = __bfloat162float(th1.y) + __bfloat162float(tl1.y);

    float zx = gx + tx + e * wv.x + bv.x;
    float zy = gy + ty + e * wv.y + bv.y;
    float zz = gz + tz + e * wv.z + bv.z;
    float zw = gw + tw + e * wv.w + bv.w;
    float4 o;
    o.x = fv.x / (1.0f + expf(-zx));
    o.y = fv.y / (1.0f + expf(-zy));
    o.z = fv.z / (1.0f + expf(-zz));
    o.w = fv.w / (1.0f + expf(-zw));
    split4_store(o, g_h0h, g_h0l, r * H3 + m * HH + j);
}

// ----------------------------------------------------------------------------
// Degree + inverse sqrt
// ----------------------------------------------------------------------------
__global__ void degree_kernel(const float* __restrict__ sp, const float* __restrict__ tp) {
    __shared__ float sh[8];
    long long b = blockIdx.y, i = blockIdx.x;
    const float* rs = sp + (b * SS + i) * SS;
    const float* rt = tp + (b * SS + i) * SS;
    float s = 0.0f;
    for (int j = threadIdx.x; j < SS; j += 256) s += rs[j] + rt[j];
    #pragma unroll
    for (int o = 16; o; o >>= 1) s += __shfl_down_sync(0xffffffffu, s, o);
    int lane = threadIdx.x & 31, w = threadIdx.x >> 5;
    if (lane == 0) sh[w] = s;
    __syncthreads();
    if (threadIdx.x == 0) {
        float D = 1.0f + 0.5f * (sh[0] + sh[1] + sh[2] + sh[3] + sh[4] + sh[5] + sh[6] + sh[7]);
        g_dsi[b * SS + i] = 1.0f / sqrtf(D + EPSV);
    }
}

__global__ void normadj_kernel(const float* __restrict__ sp, const float* __restrict__ tp) {
    long long n4 = (long long)BB * SS * SS / 4;
    for (long long g = (long long)blockIdx.x * blockDim.x + threadIdx.x; g < n4;
         g += (long long)gridDim.x * blockDim.x) {
        long long e = g * 4;
        int b = (int)(e / ((long long)SS * SS));
        long long rrem = e % ((long long)SS * SS);
        int i = (int)(rrem / SS);
        int j = (int)(rrem % SS);
        float4 a = *(const float4*)(sp + e);
        float4 c = *(const float4*)(tp + e);
        float di = g_dsi[(long long)b * SS + i];
        const float* dj = g_dsi + (long long)b * SS + j;
        float4 o;
        o.x = (0.5f * (a.x + c.x) + (j + 0 == i ? 1.0f : 0.0f)) * di * dj[0];
        o.y = (0.5f * (a.y + c.y) + (j + 1 == i ? 1.0f : 0.0f)) * di * dj[1];
        o.z = (0.5f * (a.z + c.z) + (j + 2 == i ? 1.0f : 0.0f)) * di * dj[2];
        o.w = (0.5f * (a.w + c.w) + (j + 3 == i ? 1.0f : 0.0f)) * di * dj[3];
        split4_store(o, g_adjh, g_adjl, e);
    }
}

// ----------------------------------------------------------------------------
// Classifier: out[r,c] = (hh+hl)[r,:] . WcT[c,:] + bc[c]
// ----------------------------------------------------------------------------
__global__ void classifier_kernel(const float* __restrict__ bc, float* __restrict__ out) {
    __shared__ float sh[HH];
    long long r = blockIdx.x;
    for (int k = threadIdx.x; k < HH; k += 224)
        sh[k] = __bfloat162float(g_hh[r * HH + k]) + __bfloat162float(g_hl[r * HH + k]);
    __syncthreads();
    int w = threadIdx.x >> 5, lane = threadIdx.x & 31;
    if (w < CC) {
        const float* wrow = g_WcT + w * HH;
        float s = 0.0f;
        #pragma unroll
        for (int k = lane; k < HH; k += 32) s += sh[k] * wrow[k];
        #pragma unroll
        for (int o = 16; o; o >>= 1) s += __shfl_down_sync(0xffffffffu, s, o);
        if (lane == 0) out[r * CC + w] = s + bc[w];
    }
}

// ----------------------------------------------------------------------------
// Launch
// ----------------------------------------------------------------------------
extern "C" void kernel_launch(void* const* d_in, const int* in_sizes, int n_in,
                              void* d_out, int out_size) {
    const float* text   = (const float*)d_in[0];
    const float* audio  = (const float*)d_in[1];
    const float* visual = (const float*)d_in[2];
    const float* sp     = (const float*)d_in[3];
    const float* tp     = (const float*)d_in[4];
    // d_in[5] = qmask (unused by reference)
    const float* gate_W = (const float*)d_in[6];
    const float* gate_b = (const float*)d_in[7];
    const float* W0 = (const float*)d_in[8];
    const float* b0 = (const float*)d_in[9];
    const float* W1 = (const float*)d_in[10];
    const float* b1 = (const float*)d_in[11];
    const float* W2 = (const float*)d_in[12];
    const float* b2 = (const float*)d_in[13];
    const float* Wc = (const float*)d_in[14];
    const float* bc = (const float*)d_in[15];
    float* out = (float*)d_out;

    static bool attr_done = false;
    if (!attr_done) {
        cudaFuncSetAttribute(mma_gemm<0>, cudaFuncAttributeMaxDynamicSharedMemorySize, SMEM_BYTES);
        cudaFuncSetAttribute(mma_gemm<1>, cudaFuncAttributeMaxDynamicSharedMemorySize, SMEM_BYTES);
        attr_done = true;
    }

    #define SYM(p, s) cudaGetSymbolAddress((void**)&p, s)
    __nv_bfloat16 *fh, *fl, *toth, *totl, *Gh, *Gl, *Th, *Tl, *h0h, *h0l;
    __nv_bfloat16 *adjh, *adjl, *tmph, *tmpl, *hh, *hl;
    __nv_bfloat16 *Awh, *Awl, *Whh, *Whl, *W0h, *W0l, *W1h, *W1l, *W2h, *W2l;
    SYM(fh, g_fh); SYM(fl, g_fl); SYM(toth, g_toth); SYM(totl, g_totl);
    SYM(Gh, g_Gh); SYM(Gl, g_Gl); SYM(Th, g_Th); SYM(Tl, g_Tl);
    SYM(h0h, g_h0h); SYM(h0l, g_h0l);
    SYM(adjh, g_adjh); SYM(adjl, g_adjl);
    SYM(tmph, g_tmph); SYM(tmpl, g_tmpl); SYM(hh, g_hh); SYM(hl, g_hl);
    SYM(Awh, g_Awh); SYM(Awl, g_Awl); SYM(Whh, g_Whh); SYM(Whl, g_Whl);
    SYM(W0h, g_W0h); SYM(W0l, g_W0l); SYM(W1h, g_W1h); SYM(W1l, g_W1l);
    SYM(W2h, g_W2h); SYM(W2l, g_W2l);
    #undef SYM

    // 1) prep: weights + fused entropy/split/total + wc transpose
    prep_weights<<<(HH * HH + 255) / 256, 256>>>(gate_W);
    conv_w<<<(H3 * HH / 4 + 255) / 256, 256>>>(W0, W0h, W0l, H3 * HH / 4);
    conv_w<<<(HH * HH / 4 + 255) / 256, 256>>>(W1, W1h, W1l, HH * HH / 4);
    conv_w<<<(HH * HH / 4 + 255) / 256, 256>>>(W2, W2h, W2l, HH * HH / 4);
    transpose_wc<<<(HH * CC + 255) / 256, 256>>>(Wc);
    prep_feats<<<MM, 128>>>(text, audio, visual);

    // 2) adjacency
    degree_kernel<<<dim3(SS, BB), 256>>>(sp, tp);
    normadj_kernel<<<8192, 256>>>(sp, tp);

    // 3) gating GEMMs (3 modalities in one launch via z) + total GEMM
    long long sF = (long long)MM * HH;
    dim3 gemm_grid(HH / BN, MM / BM, 1);
    dim3 gate_grid(HH / BN, MM / BM, 3);
    mma_gemm<0><<<gate_grid, 256, SMEM_BYTES>>>(fh, fl, Awh, Awl, nullptr,
                                                Gh, Gl, MM, HH, HH, sF, 0, sF);
    mma_gemm<0><<<gemm_grid, 256, SMEM_BYTES>>>(toth, totl, Whh, Whl, nullptr,
                                                Th, Tl, MM, HH, HH, 0, 0, 0);

    // 4) gate + fuse into h0 planes
    gate_fuse_kernel<<<dim3(MM, 3), 128>>>(gate_b, text, audio, visual);

    // 5) spectral GNN
    dim3 adj_grid(HH / BN, SS / BM, BB);
    long long sAdj = (long long)SS * SS, sL = (long long)SS * HH;

    mma_gemm<0><<<gemm_grid, 256, SMEM_BYTES>>>(h0h, h0l, W0h, W0l, nullptr,
                                                tmph, tmpl, MM, HH, H3, 0, 0, 0);
    mma_gemm<1><<<adj_grid, 256, SMEM_BYTES>>>(adjh, adjl, tmph, tmpl, b0,
                                               hh, hl, SS, HH, SS, sAdj, sL, sL);

    mma_gemm<0><<<gemm_grid, 256, SMEM_BYTES>>>(hh, hl, W1h, W1l, nullptr,
                                                tmph, tmpl, MM, HH, HH, 0, 0, 0);
    mma_gemm<1><<<adj_grid, 256, SMEM_BYTES>>>(adjh, adjl, tmph, tmpl, b1,
                                               hh, hl, SS, HH, SS, sAdj, sL, sL);

    mma_gemm<0><<<gemm_grid, 256, SMEM_BYTES>>>(hh, hl, W2h, W2l, nullptr,
                                                tmph, tmpl, MM, HH, HH, 0, 0, 0);
    mma_gemm<1><<<adj_grid, 256, SMEM_BYTES>>>(adjh, adjl, tmph, tmpl, b2,
                                               hh, hl, SS, HH, SS, sAdj, sL, sL);

    // 6) classifier
    classifier_kernel<<<MM, 224>>>(bc, out);
}